// round 13
// baseline (speedup 1.0000x reference)
#include <cuda_runtime.h>

#define BQ 4096
#define TT 200
#define DD 64
#define HH 64

// ---------------- scratch (static device globals: allocation-free) ----------
__device__ int g_hist[256];
__device__ int g_cursor[256];
__device__ int g_perm[BQ];
__device__ int g_qhead;

// ---------------- counting sort of rows by seq_len --------------------------
__global__ void k_hist_init() {
    int i = threadIdx.x;
    g_hist[i] = 0;
    if (i == 0) g_qhead = 0;
}

__global__ void k_hist(const int* __restrict__ sl) {
    int i = blockIdx.x * blockDim.x + threadIdx.x;
    if (i < BQ) atomicAdd(&g_hist[sl[i] & 255], 1);
}

__global__ void k_scan() {
    if (threadIdx.x == 0) {
        int s = 0;
        for (int i = 0; i < 256; i++) { int c = g_hist[i]; g_cursor[i] = s; s += c; }
    }
}

__global__ void k_scatter(const int* __restrict__ sl) {
    int i = blockIdx.x * blockDim.x + threadIdx.x;
    if (i < BQ) {
        int pos = atomicAdd(&g_cursor[sl[i] & 255], 1);
        g_perm[pos] = i;
    }
}

// ---------------- math helpers ----------------------------------------------
__device__ __forceinline__ float sigf(float v) {
    return __fdividef(1.f, 1.f + __expf(-v));
}

// ---------------- main AUGRU kernel -----------------------------------------
// One warp owns one row (sequence) at a time, pulled from a descending-L queue.
// SMEM: Wg transposed to [k][lane*4+c] (c in {0,1,2,3} -> output lane+32c),
//       Wc transposed to [k][lane*2+c] (c in {0,1}   -> output lane+32c),
//       per-warp 192-float staging buffer: [0:64)=x_t, [64:128)=h, [128:192)=r*h.
__global__ void __launch_bounds__(256, 1)
augru_main(const float* __restrict__ x, const int* __restrict__ sl,
           const float* __restrict__ att, const float* __restrict__ Wg,
           const float* __restrict__ bg, const float* __restrict__ Wc,
           const float* __restrict__ bc, float* __restrict__ out)
{
    extern __shared__ float sm[];
    float* sWg  = sm;               // 16384 floats
    float* sWc  = sm + 16384;       // 8192 floats
    float* sBg  = sm + 24576;       // 128
    float* sBc  = sm + 24704;       // 64
    float* sBuf = sm + 24768;       // 8 warps * 192

    const int tid = threadIdx.x;

    // cooperative weight load, transposed for per-lane vector LDS
    for (int i = tid; i < 128 * 128; i += 256) {
        int k = i >> 7, j = i & 127;                 // j = lane*4 + c
        sWg[i] = Wg[k * 128 + ((j & 3) << 5) + (j >> 2)];
    }
    for (int i = tid; i < 128 * 64; i += 256) {
        int k = i >> 6, j = i & 63;                  // j = lane*2 + c
        sWc[i] = Wc[k * 64 + ((j & 1) << 5) + (j >> 1)];
    }
    if (tid < 128) sBg[tid] = bg[tid];
    if (tid < 64)  sBc[tid] = bc[tid];
    __syncthreads();

    const int lane = tid & 31;
    float* rb = sBuf + (tid >> 5) * 192;

    const float bgv0 = sBg[lane], bgv1 = sBg[lane + 32];
    const float bgv2 = sBg[lane + 64], bgv3 = sBg[lane + 96];
    const float bcv0 = sBc[lane], bcv1 = sBc[lane + 32];

    for (;;) {
        int ci = 0;
        if (lane == 0) ci = atomicAdd(&g_qhead, 1);
        ci = __shfl_sync(0xffffffffu, ci, 0);
        if (ci >= BQ) break;

        const int row = g_perm[BQ - 1 - ci];         // descending L order
        const int L = sl[row];
        const float* xb = x + (size_t)row * TT * DD;
        const float* ab = att + (size_t)row * TT;
        float* ob = out + (size_t)row * TT * HH;

        float h0 = 0.f, h1 = 0.f;
        rb[64 + lane] = 0.f; rb[96 + lane] = 0.f;

        float px0 = 0.f, px1 = 0.f, pa = 0.f;
        if (L > 0) { px0 = xb[lane]; px1 = xb[lane + 32]; pa = ab[0]; }

        for (int t = 0; t < L; t++) {
            __syncwarp();                            // protect prev-iter reads / h writes
            rb[lane] = px0; rb[32 + lane] = px1;
            const float at_s = pa;
            __syncwarp();                            // x/h visible to all lanes

            // prefetch next timestep while matvecs run
            {
                const int tn = t + 1;
                if (tn < L) {
                    const float* xp = xb + tn * DD;
                    px0 = xp[lane]; px1 = xp[lane + 32]; pa = ab[tn];
                }
            }

            // ---- gate matvec: [x;h](128) @ Wg(128x128) ----
            float a0 = bgv0, a1 = bgv1, a2 = bgv2, a3 = bgv3;
            #pragma unroll 4
            for (int k4 = 0; k4 < 128; k4 += 4) {
                const float4 bv = *(const float4*)(rb + k4);
                const float* wp = sWg + k4 * 128 + lane * 4;
                float4 w0 = *(const float4*)(wp);
                float4 w1 = *(const float4*)(wp + 128);
                float4 w2 = *(const float4*)(wp + 256);
                float4 w3 = *(const float4*)(wp + 384);
                a0 += w0.x * bv.x; a1 += w0.y * bv.x; a2 += w0.z * bv.x; a3 += w0.w * bv.x;
                a0 += w1.x * bv.y; a1 += w1.y * bv.y; a2 += w1.z * bv.y; a3 += w1.w * bv.y;
                a0 += w2.x * bv.z; a1 += w2.y * bv.z; a2 += w2.z * bv.z; a3 += w2.w * bv.z;
                a0 += w3.x * bv.w; a1 += w3.y * bv.w; a2 += w3.z * bv.w; a3 += w3.w * bv.w;
            }
            const float r0 = sigf(a0), r1 = sigf(a1);
            const float u0 = sigf(a2), u1 = sigf(a3);
            rb[128 + lane] = r0 * h0;
            rb[160 + lane] = r1 * h1;
            __syncwarp();                            // r*h visible

            // ---- candidate matvec: [x; r*h](128) @ Wc(128x64) ----
            float c0 = bcv0, c1 = bcv1;
            #pragma unroll 4
            for (int k4 = 0; k4 < 64; k4 += 4) {
                const float4 bv = *(const float4*)(rb + k4);          // x part
                const float* wp = sWc + k4 * 64 + lane * 2;
                float2 w0 = *(const float2*)(wp);
                float2 w1 = *(const float2*)(wp + 64);
                float2 w2 = *(const float2*)(wp + 128);
                float2 w3 = *(const float2*)(wp + 192);
                c0 += w0.x * bv.x; c1 += w0.y * bv.x;
                c0 += w1.x * bv.y; c1 += w1.y * bv.y;
                c0 += w2.x * bv.z; c1 += w2.y * bv.z;
                c0 += w3.x * bv.w; c1 += w3.y * bv.w;
            }
            #pragma unroll 4
            for (int k4 = 0; k4 < 64; k4 += 4) {
                const float4 bv = *(const float4*)(rb + 128 + k4);    // r*h part
                const float* wp = sWc + (64 + k4) * 64 + lane * 2;
                float2 w0 = *(const float2*)(wp);
                float2 w1 = *(const float2*)(wp + 64);
                float2 w2 = *(const float2*)(wp + 128);
                float2 w3 = *(const float2*)(wp + 192);
                c0 += w0.x * bv.x; c1 += w0.y * bv.x;
                c0 += w1.x * bv.y; c1 += w1.y * bv.y;
                c0 += w2.x * bv.z; c1 += w2.y * bv.z;
                c0 += w3.x * bv.w; c1 += w3.y * bv.w;
            }
            const float ct0 = tanhf(c0), ct1 = tanhf(c1);

            const float uu0 = (1.f - at_s) * u0;
            const float uu1 = (1.f - at_s) * u1;
            h0 = uu0 * h0 + (1.f - uu0) * ct0;
            h1 = uu1 * h1 + (1.f - uu1) * ct1;

            float* op = ob + t * HH;
            op[lane] = h0; op[lane + 32] = h1;
            rb[64 + lane] = h0; rb[96 + lane] = h1;  // stage h for next step
        }

        // zero-fill masked tail (output poisoned by harness)
        float* op = ob + L * HH;
        for (int t = L; t < TT; t++) {
            op[lane] = 0.f; op[lane + 32] = 0.f;
            op += HH;
        }
    }
}

// ---------------- launch -----------------------------------------------------
extern "C" void kernel_launch(void* const* d_in, const int* in_sizes, int n_in,
                              void* d_out, int out_size)
{
    const float* x  = (const float*)d_in[0];   // rnn_input  [B,T,64]
    const int*   sl = (const int*)d_in[1];     // sequence_length [B,1]
    const float* at = (const float*)d_in[2];   // att_score  [B,T,1]
    const float* Wg = (const float*)d_in[3];   // [128,128]
    const float* bg = (const float*)d_in[4];   // [128]
    const float* Wc = (const float*)d_in[5];   // [128,64]
    const float* bc = (const float*)d_in[6];   // [64]
    float* out = (float*)d_out;                // [B,T,64]

    const int smem_bytes = (16384 + 8192 + 128 + 64 + 8 * 192) * 4; // 105216
    cudaFuncSetAttribute(augru_main, cudaFuncAttributeMaxDynamicSharedMemorySize,
                         smem_bytes);

    k_hist_init<<<1, 256>>>();
    k_hist<<<(BQ + 255) / 256, 256>>>(sl);
    k_scan<<<1, 32>>>();
    k_scatter<<<(BQ + 255) / 256, 256>>>(sl);
    augru_main<<<148, 256, smem_bytes>>>(x, sl, at, Wg, bg, Wc, bc, out);
}

// round 14
// speedup vs baseline: 1.7449x; 1.7449x over previous
#include <cuda_runtime.h>

#define BQ 4096
#define TT 200
#define DD 64
#define HH 64

// ---------------- scratch (static device globals: allocation-free) ----------
__device__ int g_hist[256];
__device__ int g_cursor[256];
__device__ int g_perm[BQ];

// ---------------- counting sort of rows by seq_len (ascending) --------------
__global__ void k_hist_init() { g_hist[threadIdx.x] = 0; }

__global__ void k_hist(const int* __restrict__ sl) {
    int i = blockIdx.x * blockDim.x + threadIdx.x;
    if (i < BQ) atomicAdd(&g_hist[sl[i] & 255], 1);
}

__global__ void k_scan() {
    if (threadIdx.x == 0) {
        int s = 0;
        for (int i = 0; i < 256; i++) { int c = g_hist[i]; g_cursor[i] = s; s += c; }
    }
}

__global__ void k_scatter(const int* __restrict__ sl) {
    int i = blockIdx.x * blockDim.x + threadIdx.x;
    if (i < BQ) {
        int pos = atomicAdd(&g_cursor[sl[i] & 255], 1);
        g_perm[pos] = i;
    }
}

// ---------------- math helpers ----------------------------------------------
__device__ __forceinline__ float sigf(float v) {
    return __fdividef(1.f, 1.f + __expf(-v));
}
__device__ __forceinline__ float tanhe(float v) {
    // tanh(x) = 1 - 2/(exp(2x)+1); saturates correctly at both ends
    return 1.f - __fdividef(2.f, __expf(2.f * v) + 1.f);
}
__device__ __forceinline__ void ffma2(unsigned long long& d,
                                      unsigned long long a, unsigned long long b) {
    asm("fma.rn.f32x2 %0, %1, %2, %0;" : "+l"(d) : "l"(a), "l"(b));
}
__device__ __forceinline__ unsigned long long pack2(float lo, float hi) {
    unsigned long long u;
    asm("mov.b64 %0, {%1,%2};" : "=l"(u) : "f"(lo), "f"(hi));
    return u;
}
__device__ __forceinline__ float pairsum(unsigned long long u) {
    float lo, hi;
    asm("mov.b64 {%0,%1}, %2;" : "=f"(lo), "=f"(hi) : "l"(u));
    return lo + hi;
}
__device__ __forceinline__ ulonglong2 ld128(const float* p) {
    return *reinterpret_cast<const ulonglong2*>(p);
}

// ---------------- main AUGRU kernel -----------------------------------------
// NR = 4 rows per warp; weights in SMEM j-major ([output][k], row padded to 132
// floats for conflict-free LDS.128); FFMA2 accumulates (even-k, odd-k) partials.
// Deterministic complementary task pairing per SMSP balances makespan.
__global__ void __launch_bounds__(256, 1)
augru_main(const float* __restrict__ x, const int* __restrict__ sl,
           const float* __restrict__ att, const float* __restrict__ Wg,
           const float* __restrict__ bg, const float* __restrict__ Wc,
           const float* __restrict__ bc, float* __restrict__ out)
{
    extern __shared__ float sm[];
    float* sWg2 = sm;                 // 128 * 132 = 16896
    float* sWc2 = sm + 16896;         // 64 * 132  = 8448
    float* sBg  = sm + 25344;         // 128
    float* sBc  = sm + 25472;         // 64
    float* sBuf = sm + 25536;         // 8 warps * 4 rows * 192

    const int tid = threadIdx.x;

    // transpose weights to j-major: sW[j*132 + k] = W[k*ncols + j]
    for (int i = tid; i < 16384; i += 256) {
        int j = i >> 7, k = i & 127;
        sWg2[j * 132 + k] = Wg[k * 128 + j];
    }
    for (int i = tid; i < 8192; i += 256) {
        int j = i >> 7, k = i & 127;
        sWc2[j * 132 + k] = Wc[k * 64 + j];
    }
    if (tid < 128) sBg[tid] = bg[tid];
    if (tid < 64)  sBc[tid] = bc[tid];
    __syncthreads();

    const int lane = tid & 31;
    const int widx = tid >> 5;

    // deterministic complementary pairing: SMSP s hosts descending-rank task s
    // (first warp) and task 1023-s (second warp, only s < 432). 1024 tasks total.
    const int sG = blockIdx.x * 4 + (widx & 3);      // global SMSP id, 0..591
    int p;
    if (widx < 4) p = sG;
    else          p = (sG < 432) ? (1023 - sG) : -1;
    if (p < 0) return;

    float* rb = sBuf + widx * 768;                   // 4 rows * 192 floats
    const float* wg0 = sWg2 + lane * 132;
    const float* wg1 = sWg2 + (lane + 32) * 132;
    const float* wg2 = sWg2 + (lane + 64) * 132;
    const float* wg3 = sWg2 + (lane + 96) * 132;
    const float* wc0 = sWc2 + lane * 132;
    const float* wc1 = sWc2 + (lane + 32) * 132;

    const float bgv0 = sBg[lane],      bgv1 = sBg[lane + 32];
    const float bgv2 = sBg[lane + 64], bgv3 = sBg[lane + 96];
    const float bcv0 = sBc[lane],      bcv1 = sBc[lane + 32];

    int rows[4], L[4];
    const float* xb[4]; const float* ab[4]; float* ob[4];
    #pragma unroll
    for (int r = 0; r < 4; r++) {
        rows[r] = g_perm[4095 - 4 * p - r];          // descending-L groups
        L[r] = sl[rows[r]];
        xb[r] = x   + (size_t)rows[r] * TT * DD;
        ab[r] = att + (size_t)rows[r] * TT;
        ob[r] = out + (size_t)rows[r] * TT * HH;
    }
    const int Lmax = L[0];                            // largest in the group

    float h0a[4], h1a[4];
    #pragma unroll
    for (int r = 0; r < 4; r++) {
        h0a[r] = 0.f; h1a[r] = 0.f;
        rb[r * 192 + 64 + lane] = 0.f;
        rb[r * 192 + 96 + lane] = 0.f;
    }

    float px0[4], px1[4], pa[4];
    if (Lmax > 0) {
        #pragma unroll
        for (int r = 0; r < 4; r++) {
            px0[r] = xb[r][lane]; px1[r] = xb[r][lane + 32]; pa[r] = ab[r][0];
        }
    }

    for (int t = 0; t < Lmax; t++) {
        __syncwarp();                                 // prev-iter rb reads done
        float at_s[4];
        #pragma unroll
        for (int r = 0; r < 4; r++) {
            rb[r * 192 + lane] = px0[r];
            rb[r * 192 + 32 + lane] = px1[r];
            at_s[r] = pa[r];
        }
        __syncwarp();                                 // x/h visible

        if (t + 1 < Lmax) {
            #pragma unroll
            for (int r = 0; r < 4; r++) {
                const float* xp = xb[r] + (t + 1) * DD;
                px0[r] = xp[lane]; px1[r] = xp[lane + 32]; pa[r] = ab[r][t + 1];
            }
        }

        // ---- gate matvec: [x;h](128) @ Wg, packed f32x2 over k pairs ----
        unsigned long long ag0[4], ag1[4], ag2[4], ag3[4];
        #pragma unroll
        for (int r = 0; r < 4; r++) {
            ag0[r] = pack2(bgv0, 0.f); ag1[r] = pack2(bgv1, 0.f);
            ag2[r] = pack2(bgv2, 0.f); ag3[r] = pack2(bgv3, 0.f);
        }
        #pragma unroll 2
        for (int k4 = 0; k4 < 128; k4 += 4) {
            const ulonglong2 w0 = ld128(wg0 + k4);
            const ulonglong2 w1 = ld128(wg1 + k4);
            const ulonglong2 w2 = ld128(wg2 + k4);
            const ulonglong2 w3 = ld128(wg3 + k4);
            #pragma unroll
            for (int r = 0; r < 4; r++) {
                const ulonglong2 v = ld128(rb + r * 192 + k4);
                ffma2(ag0[r], w0.x, v.x); ffma2(ag0[r], w0.y, v.y);
                ffma2(ag1[r], w1.x, v.x); ffma2(ag1[r], w1.y, v.y);
                ffma2(ag2[r], w2.x, v.x); ffma2(ag2[r], w2.y, v.y);
                ffma2(ag3[r], w3.x, v.x); ffma2(ag3[r], w3.y, v.y);
            }
        }
        float u0[4], u1[4];
        #pragma unroll
        for (int r = 0; r < 4; r++) {
            const float rg0 = sigf(pairsum(ag0[r]));
            const float rg1 = sigf(pairsum(ag1[r]));
            u0[r] = sigf(pairsum(ag2[r]));
            u1[r] = sigf(pairsum(ag3[r]));
            rb[r * 192 + 128 + lane] = rg0 * h0a[r];
            rb[r * 192 + 160 + lane] = rg1 * h1a[r];
        }
        __syncwarp();                                 // r*h visible

        // ---- candidate matvec: [x; r*h](128) @ Wc ----
        unsigned long long ac0[4], ac1[4];
        #pragma unroll
        for (int r = 0; r < 4; r++) {
            ac0[r] = pack2(bcv0, 0.f); ac1[r] = pack2(bcv1, 0.f);
        }
        #pragma unroll 2
        for (int k4 = 0; k4 < 64; k4 += 4) {          // x part
            const ulonglong2 w0 = ld128(wc0 + k4);
            const ulonglong2 w1 = ld128(wc1 + k4);
            #pragma unroll
            for (int r = 0; r < 4; r++) {
                const ulonglong2 v = ld128(rb + r * 192 + k4);
                ffma2(ac0[r], w0.x, v.x); ffma2(ac0[r], w0.y, v.y);
                ffma2(ac1[r], w1.x, v.x); ffma2(ac1[r], w1.y, v.y);
            }
        }
        #pragma unroll 2
        for (int k4 = 64; k4 < 128; k4 += 4) {        // r*h part (at rb+128)
            const ulonglong2 w0 = ld128(wc0 + k4);
            const ulonglong2 w1 = ld128(wc1 + k4);
            #pragma unroll
            for (int r = 0; r < 4; r++) {
                const ulonglong2 v = ld128(rb + r * 192 + 64 + k4);
                ffma2(ac0[r], w0.x, v.x); ffma2(ac0[r], w0.y, v.y);
                ffma2(ac1[r], w1.x, v.x); ffma2(ac1[r], w1.y, v.y);
            }
        }
        #pragma unroll
        for (int r = 0; r < 4; r++) {
            const float ct0 = tanhe(pairsum(ac0[r]));
            const float ct1 = tanhe(pairsum(ac1[r]));
            const float uu0 = (1.f - at_s[r]) * u0[r];
            const float uu1 = (1.f - at_s[r]) * u1[r];
            h0a[r] = uu0 * h0a[r] + (1.f - uu0) * ct0;
            h1a[r] = uu1 * h1a[r] + (1.f - uu1) * ct1;
            if (t < L[r]) {
                float* op = ob[r] + t * HH;
                op[lane] = h0a[r]; op[lane + 32] = h1a[r];
            }
            rb[r * 192 + 64 + lane] = h0a[r];         // stage h for next step
            rb[r * 192 + 96 + lane] = h1a[r];
        }
    }

    // zero-fill masked tails (output poisoned by harness)
    #pragma unroll
    for (int r = 0; r < 4; r++) {
        float* op = ob[r] + L[r] * HH;
        for (int t = L[r]; t < TT; t++) {
            op[lane] = 0.f; op[lane + 32] = 0.f;
            op += HH;
        }
    }
}

// ---------------- launch -----------------------------------------------------
extern "C" void kernel_launch(void* const* d_in, const int* in_sizes, int n_in,
                              void* d_out, int out_size)
{
    const float* x  = (const float*)d_in[0];   // rnn_input  [B,T,64]
    const int*   sl = (const int*)d_in[1];     // sequence_length [B,1]
    const float* at = (const float*)d_in[2];   // att_score  [B,T,1]
    const float* Wg = (const float*)d_in[3];   // [128,128]
    const float* bg = (const float*)d_in[4];   // [128]
    const float* Wc = (const float*)d_in[5];   // [128,64]
    const float* bc = (const float*)d_in[6];   // [64]
    float* out = (float*)d_out;                // [B,T,64]

    const int smem_bytes = (16896 + 8448 + 128 + 64 + 8 * 768) * 4; // 126720
    cudaFuncSetAttribute(augru_main, cudaFuncAttributeMaxDynamicSharedMemorySize,
                         smem_bytes);

    k_hist_init<<<1, 256>>>();
    k_hist<<<(BQ + 255) / 256, 256>>>(sl);
    k_scan<<<1, 32>>>();
    k_scatter<<<(BQ + 255) / 256, 256>>>(sl);
    augru_main<<<148, 256, smem_bytes>>>(x, sl, at, Wg, bg, Wc, bc, out);
}

// round 15
// speedup vs baseline: 1.7538x; 1.0051x over previous
#include <cuda_runtime.h>

#define BQ 4096
#define TT 200
#define DD 64
#define HH 64

// ---------------- scratch (static device globals: allocation-free) ----------
__device__ int g_hist[256];
__device__ int g_cursor[256];
__device__ int g_perm[BQ];

// ---------------- counting sort of rows by seq_len (ascending) --------------
__global__ void k_hist_init() { g_hist[threadIdx.x] = 0; }

__global__ void k_hist(const int* __restrict__ sl) {
    int i = blockIdx.x * blockDim.x + threadIdx.x;
    if (i < BQ) atomicAdd(&g_hist[sl[i] & 255], 1);
}

__global__ void k_scan() {
    if (threadIdx.x == 0) {
        int s = 0;
        for (int i = 0; i < 256; i++) { int c = g_hist[i]; g_cursor[i] = s; s += c; }
    }
}

__global__ void k_scatter(const int* __restrict__ sl) {
    int i = blockIdx.x * blockDim.x + threadIdx.x;
    if (i < BQ) {
        int pos = atomicAdd(&g_cursor[sl[i] & 255], 1);
        g_perm[pos] = i;
    }
}

// ---------------- math helpers ----------------------------------------------
__device__ __forceinline__ float sigf(float v) {
    return __fdividef(1.f, 1.f + __expf(-v));
}
__device__ __forceinline__ float tanhe(float v) {
    // tanh(x) = 1 - 2/(exp(2x)+1); saturates correctly at both ends
    return 1.f - __fdividef(2.f, __expf(2.f * v) + 1.f);
}
__device__ __forceinline__ void ffma2(unsigned long long& d,
                                      unsigned long long a, unsigned long long b) {
    asm("fma.rn.f32x2 %0, %1, %2, %0;" : "+l"(d) : "l"(a), "l"(b));
}
__device__ __forceinline__ unsigned long long pack2(float lo, float hi) {
    unsigned long long u;
    asm("mov.b64 %0, {%1,%2};" : "=l"(u) : "f"(lo), "f"(hi));
    return u;
}
__device__ __forceinline__ float pairsum(unsigned long long u) {
    float lo, hi;
    asm("mov.b64 {%0,%1}, %2;" : "=f"(lo), "=f"(hi) : "l"(u));
    return lo + hi;
}
__device__ __forceinline__ ulonglong2 ld128(const float* p) {
    return *reinterpret_cast<const ulonglong2*>(p);
}

// ---------------- main AUGRU kernel -----------------------------------------
// NR = 4 rows per warp; weights in SMEM j-major ([output][k], row padded to 132
// floats for conflict-free LDS.128); FFMA2 accumulates (even-k, odd-k) partials.
// Deterministic complementary task pairing per SMSP balances makespan.
__global__ void __launch_bounds__(256, 1)
augru_main(const float* __restrict__ x, const int* __restrict__ sl,
           const float* __restrict__ att, const float* __restrict__ Wg,
           const float* __restrict__ bg, const float* __restrict__ Wc,
           const float* __restrict__ bc, float* __restrict__ out)
{
    extern __shared__ float sm[];
    float* sWg2 = sm;                 // 128 * 132 = 16896
    float* sWc2 = sm + 16896;         // 64 * 132  = 8448
    float* sBg  = sm + 25344;         // 128
    float* sBc  = sm + 25472;         // 64
    float* sBuf = sm + 25536;         // 8 warps * 4 rows * 192

    const int tid = threadIdx.x;

    // transpose weights to j-major: sW[j*132 + k] = W[k*ncols + j]
    for (int i = tid; i < 16384; i += 256) {
        int j = i >> 7, k = i & 127;
        sWg2[j * 132 + k] = Wg[k * 128 + j];
    }
    for (int i = tid; i < 8192; i += 256) {
        int j = i >> 7, k = i & 127;
        sWc2[j * 132 + k] = Wc[k * 64 + j];
    }
    if (tid < 128) sBg[tid] = bg[tid];
    if (tid < 64)  sBc[tid] = bc[tid];
    __syncthreads();

    const int lane = tid & 31;
    const int widx = tid >> 5;

    // deterministic complementary pairing: SMSP s hosts descending-rank task s
    // (first warp) and task 1023-s (second warp, only s < 432). 1024 tasks total.
    const int sG = blockIdx.x * 4 + (widx & 3);      // global SMSP id, 0..591
    int p;
    if (widx < 4) p = sG;
    else          p = (sG < 432) ? (1023 - sG) : -1;
    if (p < 0) return;

    float* rb = sBuf + widx * 768;                   // 4 rows * 192 floats
    const float* wg0 = sWg2 + lane * 132;
    const float* wg1 = sWg2 + (lane + 32) * 132;
    const float* wg2 = sWg2 + (lane + 64) * 132;
    const float* wg3 = sWg2 + (lane + 96) * 132;
    const float* wc0 = sWc2 + lane * 132;
    const float* wc1 = sWc2 + (lane + 32) * 132;

    const float bgv0 = sBg[lane],      bgv1 = sBg[lane + 32];
    const float bgv2 = sBg[lane + 64], bgv3 = sBg[lane + 96];
    const float bcv0 = sBc[lane],      bcv1 = sBc[lane + 32];

    int rows[4], L[4];
    const float* xb[4]; const float* ab[4]; float* ob[4];
    #pragma unroll
    for (int r = 0; r < 4; r++) {
        rows[r] = g_perm[4095 - 4 * p - r];          // descending-L groups
        L[r] = sl[rows[r]];
        xb[r] = x   + (size_t)rows[r] * TT * DD;
        ab[r] = att + (size_t)rows[r] * TT;
        ob[r] = out + (size_t)rows[r] * TT * HH;
    }
    const int Lmax = L[0];                            // largest in the group

    float h0a[4], h1a[4];
    #pragma unroll
    for (int r = 0; r < 4; r++) {
        h0a[r] = 0.f; h1a[r] = 0.f;
        rb[r * 192 + 64 + lane] = 0.f;
        rb[r * 192 + 96 + lane] = 0.f;
    }

    float px0[4], px1[4], pa[4];
    if (Lmax > 0) {
        #pragma unroll
        for (int r = 0; r < 4; r++) {
            px0[r] = xb[r][lane]; px1[r] = xb[r][lane + 32]; pa[r] = ab[r][0];
        }
    }

    for (int t = 0; t < Lmax; t++) {
        __syncwarp();                                 // prev-iter rb reads done
        float at_s[4];
        #pragma unroll
        for (int r = 0; r < 4; r++) {
            rb[r * 192 + lane] = px0[r];
            rb[r * 192 + 32 + lane] = px1[r];
            at_s[r] = pa[r];
        }
        __syncwarp();                                 // x/h visible

        if (t + 1 < Lmax) {
            #pragma unroll
            for (int r = 0; r < 4; r++) {
                const float* xp = xb[r] + (t + 1) * DD;
                px0[r] = xp[lane]; px1[r] = xp[lane + 32]; pa[r] = ab[r][t + 1];
            }
        }

        // ---- gate matvec: [x;h](128) @ Wg, packed f32x2 over k pairs ----
        unsigned long long ag0[4], ag1[4], ag2[4], ag3[4];
        #pragma unroll
        for (int r = 0; r < 4; r++) {
            ag0[r] = pack2(bgv0, 0.f); ag1[r] = pack2(bgv1, 0.f);
            ag2[r] = pack2(bgv2, 0.f); ag3[r] = pack2(bgv3, 0.f);
        }
        #pragma unroll 2
        for (int k4 = 0; k4 < 128; k4 += 4) {
            const ulonglong2 w0 = ld128(wg0 + k4);
            const ulonglong2 w1 = ld128(wg1 + k4);
            const ulonglong2 w2 = ld128(wg2 + k4);
            const ulonglong2 w3 = ld128(wg3 + k4);
            #pragma unroll
            for (int r = 0; r < 4; r++) {
                const ulonglong2 v = ld128(rb + r * 192 + k4);
                ffma2(ag0[r], w0.x, v.x); ffma2(ag0[r], w0.y, v.y);
                ffma2(ag1[r], w1.x, v.x); ffma2(ag1[r], w1.y, v.y);
                ffma2(ag2[r], w2.x, v.x); ffma2(ag2[r], w2.y, v.y);
                ffma2(ag3[r], w3.x, v.x); ffma2(ag3[r], w3.y, v.y);
            }
        }
        float u0[4], u1[4];
        #pragma unroll
        for (int r = 0; r < 4; r++) {
            const float rg0 = sigf(pairsum(ag0[r]));
            const float rg1 = sigf(pairsum(ag1[r]));
            u0[r] = sigf(pairsum(ag2[r]));
            u1[r] = sigf(pairsum(ag3[r]));
            rb[r * 192 + 128 + lane] = rg0 * h0a[r];
            rb[r * 192 + 160 + lane] = rg1 * h1a[r];
        }
        __syncwarp();                                 // r*h visible

        // ---- candidate matvec: [x; r*h](128) @ Wc ----
        unsigned long long ac0[4], ac1[4];
        #pragma unroll
        for (int r = 0; r < 4; r++) {
            ac0[r] = pack2(bcv0, 0.f); ac1[r] = pack2(bcv1, 0.f);
        }
        #pragma unroll 2
        for (int k4 = 0; k4 < 64; k4 += 4) {          // x part
            const ulonglong2 w0 = ld128(wc0 + k4);
            const ulonglong2 w1 = ld128(wc1 + k4);
            #pragma unroll
            for (int r = 0; r < 4; r++) {
                const ulonglong2 v = ld128(rb + r * 192 + k4);
                ffma2(ac0[r], w0.x, v.x); ffma2(ac0[r], w0.y, v.y);
                ffma2(ac1[r], w1.x, v.x); ffma2(ac1[r], w1.y, v.y);
            }
        }
        #pragma unroll 2
        for (int k4 = 64; k4 < 128; k4 += 4) {        // r*h part (at rb+128)
            const ulonglong2 w0 = ld128(wc0 + k4);
            const ulonglong2 w1 = ld128(wc1 + k4);
            #pragma unroll
            for (int r = 0; r < 4; r++) {
                const ulonglong2 v = ld128(rb + r * 192 + 64 + k4);
                ffma2(ac0[r], w0.x, v.x); ffma2(ac0[r], w0.y, v.y);
                ffma2(ac1[r], w1.x, v.x); ffma2(ac1[r], w1.y, v.y);
            }
        }
        #pragma unroll
        for (int r = 0; r < 4; r++) {
            const float ct0 = tanhe(pairsum(ac0[r]));
            const float ct1 = tanhe(pairsum(ac1[r]));
            const float uu0 = (1.f - at_s[r]) * u0[r];
            const float uu1 = (1.f - at_s[r]) * u1[r];
            h0a[r] = uu0 * h0a[r] + (1.f - uu0) * ct0;
            h1a[r] = uu1 * h1a[r] + (1.f - uu1) * ct1;
            if (t < L[r]) {
                float* op = ob[r] + t * HH;
                op[lane] = h0a[r]; op[lane + 32] = h1a[r];
            }
            rb[r * 192 + 64 + lane] = h0a[r];         // stage h for next step
            rb[r * 192 + 96 + lane] = h1a[r];
        }
    }

    // zero-fill masked tails (output poisoned by harness)
    #pragma unroll
    for (int r = 0; r < 4; r++) {
        float* op = ob[r] + L[r] * HH;
        for (int t = L[r]; t < TT; t++) {
            op[lane] = 0.f; op[lane + 32] = 0.f;
            op += HH;
        }
    }
}

// ---------------- launch -----------------------------------------------------
extern "C" void kernel_launch(void* const* d_in, const int* in_sizes, int n_in,
                              void* d_out, int out_size)
{
    const float* x  = (const float*)d_in[0];   // rnn_input  [B,T,64]
    const int*   sl = (const int*)d_in[1];     // sequence_length [B,1]
    const float* at = (const float*)d_in[2];   // att_score  [B,T,1]
    const float* Wg = (const float*)d_in[3];   // [128,128]
    const float* bg = (const float*)d_in[4];   // [128]
    const float* Wc = (const float*)d_in[5];   // [128,64]
    const float* bc = (const float*)d_in[6];   // [64]
    float* out = (float*)d_out;                // [B,T,64]

    const int smem_bytes = (16896 + 8448 + 128 + 64 + 8 * 768) * 4; // 126720
    cudaFuncSetAttribute(augru_main, cudaFuncAttributeMaxDynamicSharedMemorySize,
                         smem_bytes);

    k_hist_init<<<1, 256>>>();
    k_hist<<<(BQ + 255) / 256, 256>>>(sl);
    k_scan<<<1, 32>>>();
    k_scatter<<<(BQ + 255) / 256, 256>>>(sl);
    augru_main<<<148, 256, smem_bytes>>>(x, sl, at, Wg, bg, Wc, bc, out);
}